// round 5
// baseline (speedup 1.0000x reference)
#include <cuda_runtime.h>
#include <cuda_bf16.h>

// FlowUpSampler convex upsampling — persistent single-wave version.
// flow: [N=8, 2, H=64, W=128] f32
// mask: [N, 576, H, W] f32 viewed as [n][k(9)][a(8)][b(8)][h][w]
// out:  [N, 2, 512, 1024] f32, out[n][c][8h+a][8w+b]
//
// Grid = 1024 blocks (one wave at 7 CTA/SM), 128 threads = w.
// Block bid owns (a,h) = decode(bid) and n in {bid>>9, +2, +4, +6}:
// tile stride 1024 advances n by 2 with (a,h) fixed. Mask loads are
// software-pipelined across b AND across tiles (9 lines/warp always in
// flight); the flow slab is double-buffered in smem and its load for the
// next tile is hidden under the current tile's b-loop.

#define H_ 64
#define W_ 128

__global__ __launch_bounds__(128, 7)
void flow_up_kernel(const float* __restrict__ flow,
                    const float* __restrict__ mask,
                    float* __restrict__ out)
{
    const int w = threadIdx.x;
    const int h = blockIdx.x & (H_ - 1);
    const int a = (blockIdx.x >> 6) & 7;
    const int n0 = blockIdx.x >> 9;          // 0 or 1; block handles n0, n0+2, n0+4, n0+6

    __shared__ float sf[2][2][3][W_ + 2];    // [buf][c][row][x], 8*flow slab

    const size_t HW = (size_t)H_ * W_;       // 8192
    const size_t KS = 64 * HW;               // k stride
    const size_t TS = (size_t)2 * 576 * HW;  // mask stride for n += 2

    // slab loader for a given n into buffer `buf`
    auto load_slab = [&](int buf, int nn) {
        for (int i = threadIdx.x; i < 2 * 3 * (W_ + 2); i += 128) {
            int c  = i / (3 * (W_ + 2));
            int r  = (i / (W_ + 2)) % 3;
            int x  = i % (W_ + 2);
            int hh = h - 1 + r;
            int ww = x - 1;
            float v = 0.0f;
            if ((unsigned)hh < H_ && (unsigned)ww < W_)
                v = 8.0f * flow[(((size_t)nn * 2 + c) * H_ + hh) * W_ + ww];
            sf[buf][c][r][x] = v;
        }
    };

    const float* mp = mask + ((size_t)n0 * 576 + (size_t)a * 8) * HW
                           + (size_t)h * W_ + w;

    // prologue: slab for first tile + prefetch b=0 mask batch
    load_slab(0, n0);
    float m[2][9];
#pragma unroll
    for (int k = 0; k < 9; k++)
        m[0][k] = __ldcs(mp + (size_t)k * KS);
    __syncthreads();

    int cur_buf = 0;

#pragma unroll 1
    for (int i = 0; i < 4; i++) {
        const int n = n0 + 2 * i;
        const bool has_next = (i < 3);

        // 3x3 patch (k = di*3+dj matches unfold ordering)
        float p0[9], p1[9];
#pragma unroll
        for (int di = 0; di < 3; di++) {
#pragma unroll
            for (int dj = 0; dj < 3; dj++) {
                p0[di * 3 + dj] = sf[cur_buf][0][di][w + dj];
                p1[di * 3 + dj] = sf[cur_buf][1][di][w + dj];
            }
        }

        // kick off next tile's slab load into the other buffer (hidden by b-loop)
        if (has_next)
            load_slab(cur_buf ^ 1, n + 2);

        const float* mp_next = mp + TS;

        float acc0[8], acc1[8];
#pragma unroll
        for (int b = 0; b < 8; b++) {
            const int cur = b & 1;
            // keep 9 loads in flight: next b, or next tile's b=0
            if (b < 7) {
                const float* mb = mp + (size_t)(b + 1) * HW;
#pragma unroll
                for (int k = 0; k < 9; k++)
                    m[cur ^ 1][k] = __ldcs(mb + (size_t)k * KS);
            } else if (has_next) {
#pragma unroll
                for (int k = 0; k < 9; k++)
                    m[cur ^ 1][k] = __ldcs(mp_next + (size_t)k * KS);
            }

            float s = 0.0f, a0 = 0.0f, a1 = 0.0f;
#pragma unroll
            for (int k = 0; k < 9; k++) {
                float e = __expf(m[cur][k]);   // softmax w/o max-sub: inputs ~N(0,1)
                s += e;
                a0 = fmaf(e, p0[k], a0);
                a1 = fmaf(e, p1[k], a1);
            }
            float r = __fdividef(1.0f, s);
            acc0[b] = a0 * r;
            acc1[b] = a1 * r;
        }

        // out[n][c][8h+a][8w+b]: 8 consecutive floats/channel -> 2x float4
        const size_t orow = (((size_t)n * 2) * (8 * H_) + (size_t)8 * h + a) * (8 * W_)
                          + (size_t)8 * w;
        const size_t cstride = (size_t)(8 * H_) * (8 * W_);
        float4* o0 = reinterpret_cast<float4*>(out + orow);
        float4* o1 = reinterpret_cast<float4*>(out + orow + cstride);
        __stcs(o0 + 0, make_float4(acc0[0], acc0[1], acc0[2], acc0[3]));
        __stcs(o0 + 1, make_float4(acc0[4], acc0[5], acc0[6], acc0[7]));
        __stcs(o1 + 0, make_float4(acc1[0], acc1[1], acc1[2], acc1[3]));
        __stcs(o1 + 1, make_float4(acc1[4], acc1[5], acc1[6], acc1[7]));

        if (has_next) {
            __syncthreads();          // next slab visible; prev buf free
            cur_buf ^= 1;
            mp = mp_next;
        }
    }
}

extern "C" void kernel_launch(void* const* d_in, const int* in_sizes, int n_in,
                              void* d_out, int out_size)
{
    const float* flow = (const float*)d_in[0];
    const float* mask = (const float*)d_in[1];
    float* out = (float*)d_out;
    (void)in_sizes; (void)n_in; (void)out_size;

    // 1024 persistent blocks = one wave at 7 CTA/SM; each does 4 tiles
    flow_up_kernel<<<1024, 128>>>(flow, mask, out);
}

// round 6
// speedup vs baseline: 1.2192x; 1.2192x over previous
#include <cuda_runtime.h>
#include <cuda_bf16.h>

// FlowUpSampler convex upsampling (RAFT-style) — R4 structure with a
// distance-2 software pipeline on the mask loads (triple-buffered batches:
// prefetch b+2 while computing b -> 18 x 128B lines per warp in flight).
// flow: [N=8, 2, H=64, W=128] f32
// mask: [N, 576, H, W] f32 viewed as [n][k(9)][a(8)][b(8)][h][w]
// out:  [N, 2, 512, 1024] f32, out[n][c][8h+a][8w+b]
//
// Block = (n, a, h); 128 threads = w. Per b: 9 coalesced scalar mask loads
// (one full 128B line per LDG per warp), softmax over k, convex combine
// with the 3x3 flow patch; accumulate all 8 b results, store 2x float4
// per channel (coalesced 1KB rows per warp).

#define H_ 64
#define W_ 128

__global__ __launch_bounds__(128, 6)
void flow_up_kernel(const float* __restrict__ flow,
                    const float* __restrict__ mask,
                    float* __restrict__ out)
{
    const int w   = threadIdx.x;
    const int bid = blockIdx.x;
    const int h = bid & (H_ - 1);
    const int a = (bid >> 6) & 7;
    const int n = bid >> 9;

    __shared__ float sf[2][3][W_ + 2];   // 8*flow, rows h-1..h+1, halo'd in w

    for (int i = threadIdx.x; i < 2 * 3 * (W_ + 2); i += 128) {
        int c  = i / (3 * (W_ + 2));
        int r  = (i / (W_ + 2)) % 3;
        int x  = i % (W_ + 2);
        int hh = h - 1 + r;
        int ww = x - 1;
        float v = 0.0f;
        if ((unsigned)hh < H_ && (unsigned)ww < W_)
            v = 8.0f * flow[(((size_t)n * 2 + c) * H_ + hh) * W_ + ww];
        sf[c][r][x] = v;
    }
    __syncthreads();

    // 3x3 patch per thread (k = di*3+dj matches unfold ordering)
    float p0[9], p1[9];
#pragma unroll
    for (int di = 0; di < 3; di++) {
#pragma unroll
        for (int dj = 0; dj < 3; dj++) {
            p0[di * 3 + dj] = sf[0][di][w + dj];
            p1[di * 3 + dj] = sf[1][di][w + dj];
        }
    }

    const size_t HW = (size_t)H_ * W_;   // 8192
    const size_t KS = 64 * HW;           // k stride in floats
    const float* mp = mask + ((size_t)n * 576 + (size_t)a * 8) * HW
                           + (size_t)h * W_ + w;

    // triple-buffered mask batches: prefetch distance 2
    float m[3][9];
#pragma unroll
    for (int k = 0; k < 9; k++)
        m[0][k] = __ldcs(mp + (size_t)k * KS);               // b = 0
#pragma unroll
    for (int k = 0; k < 9; k++)
        m[1][k] = __ldcs(mp + HW + (size_t)k * KS);          // b = 1

    float acc0[8], acc1[8];
#pragma unroll
    for (int b = 0; b < 8; b++) {
        // prefetch b+2 BEFORE this b's compute chain
        if (b < 6) {
            const float* mb = mp + (size_t)(b + 2) * HW;
            float* md = m[(b + 2) % 3];
#pragma unroll
            for (int k = 0; k < 9; k++)
                md[k] = __ldcs(mb + (size_t)k * KS);
        }

        const float* mc = m[b % 3];
        float s = 0.0f, a0 = 0.0f, a1 = 0.0f;
#pragma unroll
        for (int k = 0; k < 9; k++) {
            float e = __expf(mc[k]);     // softmax w/o max-sub: inputs ~N(0,1)
            s += e;
            a0 = fmaf(e, p0[k], a0);
            a1 = fmaf(e, p1[k], a1);
        }
        float r = __fdividef(1.0f, s);
        acc0[b] = a0 * r;
        acc1[b] = a1 * r;
    }

    // out[n][c][8h+a][8w+b]: 8 consecutive floats per channel -> 2x float4
    const size_t orow = (((size_t)n * 2) * (8 * H_) + (size_t)8 * h + a) * (8 * W_)
                      + (size_t)8 * w;
    const size_t cstride = (size_t)(8 * H_) * (8 * W_);
    float4* o0 = reinterpret_cast<float4*>(out + orow);
    float4* o1 = reinterpret_cast<float4*>(out + orow + cstride);
    __stcs(o0 + 0, make_float4(acc0[0], acc0[1], acc0[2], acc0[3]));
    __stcs(o0 + 1, make_float4(acc0[4], acc0[5], acc0[6], acc0[7]));
    __stcs(o1 + 0, make_float4(acc1[0], acc1[1], acc1[2], acc1[3]));
    __stcs(o1 + 1, make_float4(acc1[4], acc1[5], acc1[6], acc1[7]));
}

extern "C" void kernel_launch(void* const* d_in, const int* in_sizes, int n_in,
                              void* d_out, int out_size)
{
    const float* flow = (const float*)d_in[0];
    const float* mask = (const float*)d_in[1];
    float* out = (float*)d_out;
    (void)in_sizes; (void)n_in; (void)out_size;

    flow_up_kernel<<<4096, 128>>>(flow, mask, out);
}